// round 15
// baseline (speedup 1.0000x reference)
#include <cuda_runtime.h>
#include <cuda_fp16.h>
#include <cstdint>
#include <math.h>

#define M_TOK 4096   // B*S
#define DMODEL 1024
#define NHEAD 16
#define HDIM 64

// fp32 scratch for the LN input
__device__ float g_ob[(size_t)M_TOK * DMODEL];
// fp16 operands
__device__ __half g_xf[(size_t)M_TOK * DMODEL];
__device__ __half g_qf[(size_t)M_TOK * DMODEL], g_kf[(size_t)M_TOK * DMODEL];
__device__ __half g_vf[(size_t)M_TOK * DMODEL], g_af[(size_t)M_TOK * DMODEL];
__device__ __half g_wf[4][(size_t)DMODEL * DMODEL];

// ---------------------------------------------------------------------------
// PTX helpers valid on base sm_103 target
// ---------------------------------------------------------------------------
__device__ __forceinline__ uint32_t smem_to_u32(const void* p) {
    uint32_t a;
    asm("{ .reg .u64 t; cvta.to.shared.u64 t, %1; cvt.u32.u64 %0, t; }" : "=r"(a) : "l"(p));
    return a;
}
__device__ __forceinline__ void cp16(uint32_t dst, const void* src) {
    asm volatile("cp.async.cg.shared.global [%0], [%1], 16;" :: "r"(dst), "l"(src));
}
__device__ __forceinline__ void cp_commit() {
    asm volatile("cp.async.commit_group;" ::: "memory");
}
template <int N>
__device__ __forceinline__ void cp_wait() {
    asm volatile("cp.async.wait_group %0;" :: "n"(N) : "memory");
}
__device__ __forceinline__ void ldsm4(uint32_t* r, uint32_t addr) {
    asm volatile("ldmatrix.sync.aligned.m8n8.x4.shared.b16 {%0,%1,%2,%3}, [%4];"
                 : "=r"(r[0]), "=r"(r[1]), "=r"(r[2]), "=r"(r[3]) : "r"(addr));
}
__device__ __forceinline__ void ldsm4t(uint32_t* r, uint32_t addr) {
    asm volatile("ldmatrix.sync.aligned.m8n8.x4.trans.shared.b16 {%0,%1,%2,%3}, [%4];"
                 : "=r"(r[0]), "=r"(r[1]), "=r"(r[2]), "=r"(r[3]) : "r"(addr));
}
__device__ __forceinline__ void mma16816(float* c, const uint32_t* a, const uint32_t* b) {
    asm volatile(
        "mma.sync.aligned.m16n8k16.row.col.f32.f16.f16.f32 "
        "{%0,%1,%2,%3}, {%4,%5,%6,%7}, {%8,%9}, {%0,%1,%2,%3};"
        : "+f"(c[0]), "+f"(c[1]), "+f"(c[2]), "+f"(c[3])
        : "r"(a[0]), "r"(a[1]), "r"(a[2]), "r"(a[3]), "r"(b[0]), "r"(b[1]));
}
__device__ __forceinline__ uint32_t pack_h2(float x, float y) {
    __half2 h = __floats2half2_rn(x, y);
    return *reinterpret_cast<uint32_t*>(&h);
}
// raw ex2.approx: one MUFU op, ex2(-inf) = 0
__device__ __forceinline__ float ex2(float x) {
    float y;
    asm("ex2.approx.f32 %0, %1;" : "=f"(y) : "f"(x));
    return y;
}

// ---------------------------------------------------------------------------
// Fused fp32 -> fp16 convert; 4 independent float4 units per thread (MLP=4).
// ---------------------------------------------------------------------------
__global__ __launch_bounds__(256) void conv_all(
    const float* __restrict__ X,
    const float* __restrict__ Wq, const float* __restrict__ Wk,
    const float* __restrict__ Wv, const float* __restrict__ Wo,
    __half* __restrict__ xf, __half* __restrict__ wf)
{
    const int base = blockIdx.x * 1024 + threadIdx.x;
#pragma unroll
    for (int u = 0; u < 4; u++) {
        int i = base + u * 256;               // 0 .. 2^21-1
        const float* src;
        __half* dst;
        if (i < (1 << 20)) {
            src = X + (size_t)i * 4;
            dst = xf + (size_t)i * 4;
        } else {
            int j = i - (1 << 20);
            int sel = j >> 18;
            int jj = j & ((1 << 18) - 1);
            const float* w4[4] = {Wq, Wk, Wv, Wo};
            src = w4[sel] + (size_t)jj * 4;
            dst = wf + (size_t)sel * DMODEL * DMODEL + (size_t)jj * 4;
        }
        float4 v = *(const float4*)src;
        uint2 o;
        o.x = pack_h2(v.x, v.y);
        o.y = pack_h2(v.z, v.w);
        *(uint2*)dst = o;
    }
}

// ---------------------------------------------------------------------------
// Core A (qkv): 128x128 CTA tile, BK=32, 8 warps 2x4, warp 64x32.
// 3-stage ring; kk-level fragment double-buffering. (R12-R14 verified.)
// ---------------------------------------------------------------------------
#define STG128 20480
struct Gemm128 {
    uint32_t sbase;
    int tid, lane, wm, wn;
    uint32_t arow, ahalf, brow, bhalf;
    float c[4][4][4];

    __device__ __forceinline__ void init(uint32_t sb, int t) {
        sbase = sb; tid = t; lane = t & 31;
        int wid = t >> 5; wm = wid >> 2; wn = wid & 3;
        arow = lane & 15; ahalf = (uint32_t)(lane >> 4);
        brow = (lane & 7) | (((uint32_t)lane >> 4) << 3);
        bhalf = ((uint32_t)lane >> 3) & 1;
#pragma unroll
        for (int i = 0; i < 4; i++)
#pragma unroll
            for (int j = 0; j < 4; j++)
#pragma unroll
                for (int q = 0; q < 4; q++) c[i][j][q] = 0.f;
    }
    __device__ __forceinline__ void load_stage(const __half* A, const __half* B,
                                               int m0, int n0, int kt, int st) {
        const uint32_t dstb = sbase + st * STG128;
#pragma unroll
        for (int i = 0; i < 4; i++) {
            int cid = i * 256 + tid;            // 0..1023
            int t   = cid >> 9;                 // 0:A 1:B
            int row = (cid >> 2) & 127;
            int kc  = cid & 3;
            const __half* src = t ? B : A;
            const int gbase = t ? n0 : m0;
            cp16(dstb + t * 10240 + row * 80 + kc * 16,
                 src + (size_t)(gbase + row) * DMODEL + kt + kc * 8);
        }
    }
    __device__ __forceinline__ void run(const __half* A, const __half* B, int m0, int n0) {
        const int NK = DMODEL / 32;
        load_stage(A, B, m0, n0, 0, 0); cp_commit();
        load_stage(A, B, m0, n0, 32, 1); cp_commit();
        for (int ch = 0; ch < NK; ch++) {
            if (ch + 1 < NK) cp_wait<1>(); else cp_wait<0>();
            __syncthreads();
            const uint32_t tb = sbase + (ch % 3) * STG128;
            const uint32_t abase = tb + (wm * 64 + arow) * 80 + ahalf * 16;
            const uint32_t bbase = tb + 10240 + (wn * 32 + brow) * 80 + bhalf * 16;
            uint32_t ah[2][4][4], bb[2][2][4];
#pragma unroll
            for (int i = 0; i < 4; i++) ldsm4(ah[0][i], abase + i * (16 * 80));
#pragma unroll
            for (int j = 0; j < 2; j++) ldsm4(bb[0][j], bbase + j * (16 * 80));
            if (ch + 2 < NK) {
                load_stage(A, B, m0, n0, (ch + 2) * 32, (ch + 2) % 3);
                cp_commit();
            }
#pragma unroll
            for (int kk = 0; kk < 2; kk++) {
                const int cur = kk & 1, nxt = cur ^ 1;
                if (kk < 1) {
#pragma unroll
                    for (int i = 0; i < 4; i++) ldsm4(ah[nxt][i], abase + i * (16 * 80) + 32);
#pragma unroll
                    for (int j = 0; j < 2; j++) ldsm4(bb[nxt][j], bbase + j * (16 * 80) + 32);
                }
#pragma unroll
                for (int i = 0; i < 4; i++)
#pragma unroll
                    for (int j = 0; j < 4; j++)
                        mma16816(c[i][j], ah[cur][i], &bb[cur][j >> 1][(j & 1) * 2]);
            }
        }
    }
};

// Fused QKV projection: grid.x = 24 (seg = bx>>3, n0 = (bx&7)*128), grid.y = 32.
__global__ __launch_bounds__(256) void gemm_qkv(
    const __half* __restrict__ Xf, const __half* __restrict__ Wf,
    const float* __restrict__ bq, const float* __restrict__ bk,
    const float* __restrict__ bv,
    __half* __restrict__ Qf, __half* __restrict__ Kf, __half* __restrict__ Vf)
{
    extern __shared__ __align__(128) char smem[];
    const int seg = blockIdx.x >> 3;
    const int n0  = (blockIdx.x & 7) * 128;
    const int m0  = blockIdx.y * 128;
    const __half* B = Wf + (size_t)seg * DMODEL * DMODEL;
    const float* bias = (seg == 0) ? bq : (seg == 1) ? bk : bv;
    __half* Ch = (seg == 0) ? Qf : (seg == 1) ? Kf : Vf;
    // Q scale folds HD^-0.5 AND log2(e) so attention can use raw ex2.
    const float alpha = (seg == 0) ? 0.18033688f : 1.f;   // 0.125 * log2(e)

    Gemm128 g;
    g.init(smem_to_u32(smem), threadIdx.x);
    g.run(Xf, B, m0, n0);

    const int lane = g.lane;
#pragma unroll
    for (int i = 0; i < 4; i++) {
        const int r = m0 + g.wm * 64 + i * 16 + (lane >> 2);
#pragma unroll
        for (int j = 0; j < 4; j++) {
            const int col = n0 + g.wn * 32 + j * 8 + (lane & 3) * 2;
            const float b0 = bias[col], b1 = bias[col + 1];
            *(uint32_t*)(Ch + (size_t)r * DMODEL + col) =
                pack_h2(alpha * (g.c[i][j][0] + b0), alpha * (g.c[i][j][1] + b1));
            *(uint32_t*)(Ch + (size_t)(r + 8) * DMODEL + col) =
                pack_h2(alpha * (g.c[i][j][2] + b0), alpha * (g.c[i][j][3] + b1));
        }
    }
}

// ---------------------------------------------------------------------------
// Core B (out, R9-R14 verified): 128x256 CTA tile, warp 64x64,
// batch-fragment scheduling. Stage 30720 B, 3-stage ring.
// ---------------------------------------------------------------------------
#define STG256 30720
struct Gemm256 {
    uint32_t sbase;
    int tid, lane, wm, wn;
    uint32_t arow, ahalf, brow, bhalf;
    float c[4][8][4];

    __device__ __forceinline__ void init(uint32_t sb, int t) {
        sbase = sb; tid = t; lane = t & 31;
        int wid = t >> 5; wm = wid >> 2; wn = wid & 3;
        arow = lane & 15; ahalf = (uint32_t)(lane >> 4);
        brow = (lane & 7) | (((uint32_t)lane >> 4) << 3);
        bhalf = ((uint32_t)lane >> 3) & 1;
#pragma unroll
        for (int i = 0; i < 4; i++)
#pragma unroll
            for (int j = 0; j < 8; j++)
#pragma unroll
                for (int q = 0; q < 4; q++) c[i][j][q] = 0.f;
    }
    __device__ __forceinline__ void load_stage(const __half* A, const __half* B,
                                               int m0, int n0, int kt, int st) {
        const uint32_t dstb = sbase + st * STG256;
#pragma unroll
        for (int i = 0; i < 2; i++) {
            int cid = i * 256 + tid;
            int row = (cid & 7) | ((cid >> 5) << 3);
            int kc  = (cid >> 3) & 3;
            cp16(dstb + row * 80 + kc * 16,
                 A + (size_t)(m0 + row) * DMODEL + kt + kc * 8);
        }
#pragma unroll
        for (int i = 0; i < 4; i++) {
            int cid = i * 256 + tid;
            int row = (cid & 7) | ((cid >> 5) << 3);
            int kc  = (cid >> 3) & 3;
            cp16(dstb + 10240 + row * 80 + kc * 16,
                 B + (size_t)(n0 + row) * DMODEL + kt + kc * 8);
        }
    }
    __device__ __forceinline__ void run(const __half* A, const __half* B, int m0, int n0) {
        const int NK = DMODEL / 32;
        load_stage(A, B, m0, n0, 0, 0); cp_commit();
        load_stage(A, B, m0, n0, 32, 1); cp_commit();
        for (int ch = 0; ch < NK; ch++) {
            if (ch + 1 < NK) cp_wait<1>(); else cp_wait<0>();
            __syncthreads();
            const uint32_t tb = sbase + (ch % 3) * STG256;
            uint32_t ah[2][4][4], bb[2][4][4];
#pragma unroll
            for (int kk = 0; kk < 2; kk++) {
                const uint32_t koff = kk * 32;
#pragma unroll
                for (int i = 0; i < 4; i++)
                    ldsm4(ah[kk][i], tb + (wm * 64 + i * 16 + arow) * 80 + koff + ahalf * 16);
#pragma unroll
                for (int j = 0; j < 4; j++)
                    ldsm4(bb[kk][j], tb + 10240 + (wn * 64 + j * 16 + brow) * 80 + koff + bhalf * 16);
            }
            if (ch + 2 < NK) {
                load_stage(A, B, m0, n0, (ch + 2) * 32, (ch + 2) % 3);
                cp_commit();
            }
#pragma unroll
            for (int kk = 0; kk < 2; kk++)
#pragma unroll
                for (int i = 0; i < 4; i++)
#pragma unroll
                    for (int j = 0; j < 8; j++)
                        mma16816(c[i][j], ah[kk][i], &bb[kk][j >> 1][(j & 1) * 2]);
        }
    }
};

// Output projection: fp32 output. grid (4, 32) = 128 CTAs (one wave).
__global__ __launch_bounds__(256) void gemm_out(
    const __half* __restrict__ A, const __half* __restrict__ B,
    const float* __restrict__ bias, float* __restrict__ Cf)
{
    extern __shared__ __align__(128) char smem[];
    const int n0 = blockIdx.x * 256;
    const int m0 = blockIdx.y * 128;

    Gemm256 g;
    g.init(smem_to_u32(smem), threadIdx.x);
    g.run(A, B, m0, n0);

    const int lane = g.lane;
#pragma unroll
    for (int i = 0; i < 4; i++) {
        const int r = m0 + g.wm * 64 + i * 16 + (lane >> 2);
#pragma unroll
        for (int j = 0; j < 8; j++) {
            const int col = n0 + g.wn * 64 + j * 8 + (lane & 3) * 2;
            const float b0 = bias[col], b1 = bias[col + 1];
            float2 w0, w1;
            w0.x = g.c[i][j][0] + b0; w0.y = g.c[i][j][1] + b1;
            w1.x = g.c[i][j][2] + b0; w1.y = g.c[i][j][3] + b1;
            *(float2*)(Cf + (size_t)r * DMODEL + col)       = w0;
            *(float2*)(Cf + (size_t)(r + 8) * DMODEL + col) = w1;
        }
    }
}

// ---------------------------------------------------------------------------
// fp16 HMMA flash attention, causal, NO-MAX streaming softmax with raw ex2.
// Q fragments hoisted to registers ONCE (kt==0) — S-loop issues only K ldsm.
// exp computed inside the PV loop (MUFU overlaps HMMA).
// CTA = (128-q tile, head, batch), 256 thr. K/V tiles 64 rows, 3-stage ring.
// smem (73728 B): Q@0 (128x144); stage s at 18432 + s*18432: K@+0, V@+9216.
// ---------------------------------------------------------------------------
__global__ __launch_bounds__(256) void attn_tc(
    const __half* __restrict__ Q, const __half* __restrict__ K,
    const __half* __restrict__ V, __half* __restrict__ O)
{
    extern __shared__ __align__(128) char smem[];
    const uint32_t sb = smem_to_u32(smem);
    const int tid = threadIdx.x, lane = tid & 31, w = tid >> 5;
    const int qt = 15 - blockIdx.x;      // heavy tiles first
    const int h  = blockIdx.y;
    const int b  = blockIdx.z;
    const size_t tokq = (size_t)b * 2048 + qt * 128;
    const size_t hoff = (size_t)h * HDIM;

    auto load_kv = [&](int kt, int s) {
        const size_t tokk = (size_t)b * 2048 + kt * 64;
        const uint32_t db = sb + 18432 + s * 18432;
#pragma unroll
        for (int i = 0; i < 4; i++) {
            int c = tid + i * 256;
            int t = c >> 9, r = (c >> 3) & 63, kc = c & 7;
            const __half* src = t ? V : K;
            cp16(db + t * 9216 + r * 144 + kc * 16, src + (tokk + r) * DMODEL + hoff + kc * 8);
        }
    };

#pragma unroll
    for (int i = 0; i < 4; i++) {
        int c = tid + i * 256;
        int r = c >> 3, kc = c & 7;
        cp16(sb + r * 144 + kc * 16, Q + (tokq + r) * DMODEL + hoff + kc * 8);
    }
    const int kmax = 2 * qt + 1;
    load_kv(0, 0); cp_commit();
    load_kv(1, 1); cp_commit();

    float o[8][4];
#pragma unroll
    for (int nb = 0; nb < 8; nb++)
#pragma unroll
        for (int q = 0; q < 4; q++) o[nb][q] = 0.f;
    float l0 = 0.f, l1 = 0.f;

    const uint32_t qa  = (uint32_t)((w * 16 + (lane & 15)) * 144 + (lane >> 4) * 16);
    const uint32_t kbr = (uint32_t)((lane & 7) | ((lane >> 4) << 3));
    const uint32_t kbh = (uint32_t)(((lane >> 3) & 1) * 16);
    const uint32_t vkr = (uint32_t)((lane & 7) + ((lane >> 3) & 1) * 8);
    const uint32_t vnc = (uint32_t)(((lane >> 4) & 1) * 8);

    const int gr0 = qt * 128 + w * 16 + (lane >> 2);
    const int gr1 = gr0 + 8;

    uint32_t aqall[4][4];   // Q fragments, loaded once at kt==0, live all loop

    for (int kt = 0; kt <= kmax; kt++) {
        if (kt + 1 <= kmax) cp_wait<1>(); else cp_wait<0>();
        __syncthreads();
        if (kt + 2 <= kmax) { load_kv(kt + 2, (kt + 2) % 3); cp_commit(); }

        const uint32_t KB = sb + 18432 + (kt % 3) * 18432;
        const uint32_t VB = KB + 9216;

        if (kt == 0) {   // hoist: Q is ready after the first group wait
#pragma unroll
            for (int kk = 0; kk < 4; kk++)
                ldsm4(aqall[kk], sb + qa + kk * 32);
        }

        // ---- S = Q K^T (K fragments double-buffered; Q in registers) ----
        float sfr[8][4];
#pragma unroll
        for (int nb = 0; nb < 8; nb++)
#pragma unroll
            for (int q = 0; q < 4; q++) sfr[nb][q] = 0.f;

        uint32_t bk4[2][4][4];
#pragma unroll
        for (int t = 0; t < 4; t++)
            ldsm4(bk4[0][t], KB + (t * 16 + kbr) * 144 + kbh);
#pragma unroll
        for (int kk = 0; kk < 4; kk++) {
            const int cur = kk & 1, nxt = cur ^ 1;
            if (kk < 3) {
#pragma unroll
                for (int t = 0; t < 4; t++)
                    ldsm4(bk4[nxt][t], KB + (t * 16 + kbr) * 144 + (kk + 1) * 32 + kbh);
            }
#pragma unroll
            for (int nb = 0; nb < 8; nb++)
                mma16816(sfr[nb], aqall[kk], &bk4[cur][nb >> 1][(nb & 1) * 2]);
        }

        // causal mask (only the last two K tiles can intersect the diagonal)
        if (kt >= kmax - 1) {
            const int cb = kt * 64;
#pragma unroll
            for (int nb = 0; nb < 8; nb++) {
                const int cc = cb + nb * 8 + (lane & 3) * 2;
                if (cc     > gr0) sfr[nb][0] = -INFINITY;
                if (cc + 1 > gr0) sfr[nb][1] = -INFINITY;
                if (cc     > gr1) sfr[nb][2] = -INFINITY;
                if (cc + 1 > gr1) sfr[nb][3] = -INFINITY;
            }
        }

        // ---- O += P V; exp (ex2) per-kk inside the loop (MUFU overlap) ----
        uint32_t vv[2][4][4];
#pragma unroll
        for (int t = 0; t < 4; t++)
            ldsm4t(vv[0][t], VB + vkr * 144 + (t * 16 + vnc) * 2);
#pragma unroll
        for (int kk = 0; kk < 4; kk++) {
            const int cur = kk & 1, nxt = cur ^ 1;
            if (kk < 3) {
#pragma unroll
                for (int t = 0; t < 4; t++)
                    ldsm4t(vv[nxt][t], VB + ((kk + 1) * 16 + vkr) * 144 + (t * 16 + vnc) * 2);
            }
            float* p0 = sfr[2 * kk];
            float* p1 = sfr[2 * kk + 1];
            p0[0] = ex2(p0[0]); p0[1] = ex2(p0[1]);
            p0[2] = ex2(p0[2]); p0[3] = ex2(p0[3]);
            p1[0] = ex2(p1[0]); p1[1] = ex2(p1[1]);
            p1[2] = ex2(p1[2]); p1[3] = ex2(p1[3]);
            l0 += p0[0] + p0[1] + p1[0] + p1[1];
            l1 += p0[2] + p0[3] + p1[2] + p1[3];
            uint32_t ap[4];
            ap[0] = pack_h2(p0[0], p0[1]);
            ap[1] = pack_h2(p0[2], p0[3]);
            ap[2] = pack_h2(p1[0], p1[1]);
            ap[3] = pack_h2(p1[2], p1[3]);
#pragma unroll
            for (int nb = 0; nb < 8; nb++)
                mma16816(o[nb], ap, &vv[cur][nb >> 1][(nb & 1) * 2]);
        }
    }

    // row-sum reduce across the 4-lane quad, then normalize + store
    l0 += __shfl_xor_sync(0xffffffffu, l0, 1);
    l0 += __shfl_xor_sync(0xffffffffu, l0, 2);
    l1 += __shfl_xor_sync(0xffffffffu, l1, 1);
    l1 += __shfl_xor_sync(0xffffffffu, l1, 2);
    const float i0 = 1.f / l0, i1 = 1.f / l1;
    const size_t r0 = tokq + w * 16 + (lane >> 2);
    const size_t r1 = r0 + 8;
#pragma unroll
    for (int nb = 0; nb < 8; nb++) {
        const size_t col = hoff + nb * 8 + (lane & 3) * 2;
        *(uint32_t*)(O + r0 * DMODEL + col) = pack_h2(o[nb][0] * i0, o[nb][1] * i0);
        *(uint32_t*)(O + r1 * DMODEL + col) = pack_h2(o[nb][2] * i1, o[nb][3] * i1);
    }
}

// ---------------------------------------------------------------------------
// Residual add + LayerNorm
// ---------------------------------------------------------------------------
__global__ __launch_bounds__(256) void ln_kernel(
    const float* __restrict__ Osrc, const float* __restrict__ X,
    const float* __restrict__ g, const float* __restrict__ beta,
    float* __restrict__ out)
{
    const int row = blockIdx.x;
    const int tid = threadIdx.x;
    const float* o = Osrc + (size_t)row * DMODEL;
    const float* x = X + (size_t)row * DMODEL;

    float v[4];
    float s = 0.f, s2 = 0.f;
#pragma unroll
    for (int i = 0; i < 4; i++) {
        int c = tid + i * 256;
        float t = o[c] + x[c];
        v[i] = t; s += t; s2 += t * t;
    }
#pragma unroll
    for (int off = 16; off; off >>= 1) {
        s  += __shfl_xor_sync(0xffffffffu, s, off);
        s2 += __shfl_xor_sync(0xffffffffu, s2, off);
    }
    __shared__ float red[18];
    int w = tid >> 5;
    if ((tid & 31) == 0) { red[w] = s; red[8 + w] = s2; }
    __syncthreads();
    if (tid == 0) {
        float S = 0.f, S2 = 0.f;
        for (int k = 0; k < 8; k++) { S += red[k]; S2 += red[8 + k]; }
        red[16] = S; red[17] = S2;
    }
    __syncthreads();
    float mu   = red[16] * (1.f / 1024.f);
    float var  = red[17] * (1.f / 1024.f) - mu * mu;
    float rstd = rsqrtf(var + 1e-5f);
#pragma unroll
    for (int i = 0; i < 4; i++) {
        int c = tid + i * 256;
        out[(size_t)row * DMODEL + c] = (v[i] - mu) * rstd * g[c] + beta[c];
    }
}

// ---------------------------------------------------------------------------
extern "C" void kernel_launch(void* const* d_in, const int* in_sizes, int n_in,
                              void* d_out, int out_size)
{
    const float* X  = (const float*)d_in[0];
    const float* Wq = (const float*)d_in[1];
    const float* bq = (const float*)d_in[2];
    const float* Wk = (const float*)d_in[3];
    const float* bk = (const float*)d_in[4];
    const float* Wv = (const float*)d_in[5];
    const float* bv = (const float*)d_in[6];
    const float* Wo = (const float*)d_in[7];
    const float* bo = (const float*)d_in[8];
    const float* lg = (const float*)d_in[9];
    const float* lb = (const float*)d_in[10];
    float* out = (float*)d_out;

    float* Ob = nullptr;
    cudaGetSymbolAddress((void**)&Ob, g_ob);
    __half *xf, *qf, *kf, *vf, *af, *wf;
    cudaGetSymbolAddress((void**)&xf, g_xf);
    cudaGetSymbolAddress((void**)&qf, g_qf);
    cudaGetSymbolAddress((void**)&kf, g_kf);
    cudaGetSymbolAddress((void**)&vf, g_vf);
    cudaGetSymbolAddress((void**)&af, g_af);
    cudaGetSymbolAddress((void**)&wf, g_wf);

    const size_t WS = (size_t)DMODEL * DMODEL;

    conv_all<<<(1 << 21) / 1024, 256>>>(X, Wq, Wk, Wv, Wo, xf, wf);

    cudaFuncSetAttribute(gemm_qkv, cudaFuncAttributeMaxDynamicSharedMemorySize, 3 * STG128);
    cudaFuncSetAttribute(gemm_out, cudaFuncAttributeMaxDynamicSharedMemorySize, 3 * STG256);

    gemm_qkv<<<dim3(24, 32), 256, 3 * STG128>>>(xf, wf, bq, bk, bv, qf, kf, vf);

    const int attn_smem = 18432 + 3 * 18432;    // 73,728 B
    cudaFuncSetAttribute(attn_tc, cudaFuncAttributeMaxDynamicSharedMemorySize, attn_smem);
    attn_tc<<<dim3(16, NHEAD, 2), 256, attn_smem>>>(qf, kf, vf, af);

    gemm_out<<<dim3(4, 32), 256, 3 * STG256>>>(af, wf + 3 * WS, bo, Ob);

    ln_kernel<<<M_TOK, 256>>>(Ob, X, lg, lb, out);
}

// round 16
// speedup vs baseline: 1.0195x; 1.0195x over previous
#include <cuda_runtime.h>
#include <cuda_fp16.h>
#include <cstdint>
#include <math.h>

#define M_TOK 4096   // B*S
#define DMODEL 1024
#define NHEAD 16
#define HDIM 64

// fp32 scratch for the LN input
__device__ float g_ob[(size_t)M_TOK * DMODEL];
// fp16 operands
__device__ __half g_xf[(size_t)M_TOK * DMODEL];
__device__ __half g_qf[(size_t)M_TOK * DMODEL], g_kf[(size_t)M_TOK * DMODEL];
__device__ __half g_vf[(size_t)M_TOK * DMODEL], g_af[(size_t)M_TOK * DMODEL];
__device__ __half g_wf[4][(size_t)DMODEL * DMODEL];

// ---------------------------------------------------------------------------
// PTX helpers valid on base sm_103 target
// ---------------------------------------------------------------------------
__device__ __forceinline__ uint32_t smem_to_u32(const void* p) {
    uint32_t a;
    asm("{ .reg .u64 t; cvta.to.shared.u64 t, %1; cvt.u32.u64 %0, t; }" : "=r"(a) : "l"(p));
    return a;
}
__device__ __forceinline__ void cp16(uint32_t dst, const void* src) {
    asm volatile("cp.async.cg.shared.global [%0], [%1], 16;" :: "r"(dst), "l"(src));
}
__device__ __forceinline__ void cp_commit() {
    asm volatile("cp.async.commit_group;" ::: "memory");
}
template <int N>
__device__ __forceinline__ void cp_wait() {
    asm volatile("cp.async.wait_group %0;" :: "n"(N) : "memory");
}
__device__ __forceinline__ void ldsm4(uint32_t* r, uint32_t addr) {
    asm volatile("ldmatrix.sync.aligned.m8n8.x4.shared.b16 {%0,%1,%2,%3}, [%4];"
                 : "=r"(r[0]), "=r"(r[1]), "=r"(r[2]), "=r"(r[3]) : "r"(addr));
}
__device__ __forceinline__ void ldsm4t(uint32_t* r, uint32_t addr) {
    asm volatile("ldmatrix.sync.aligned.m8n8.x4.trans.shared.b16 {%0,%1,%2,%3}, [%4];"
                 : "=r"(r[0]), "=r"(r[1]), "=r"(r[2]), "=r"(r[3]) : "r"(addr));
}
__device__ __forceinline__ void mma16816(float* c, const uint32_t* a, const uint32_t* b) {
    asm volatile(
        "mma.sync.aligned.m16n8k16.row.col.f32.f16.f16.f32 "
        "{%0,%1,%2,%3}, {%4,%5,%6,%7}, {%8,%9}, {%0,%1,%2,%3};"
        : "+f"(c[0]), "+f"(c[1]), "+f"(c[2]), "+f"(c[3])
        : "r"(a[0]), "r"(a[1]), "r"(a[2]), "r"(a[3]), "r"(b[0]), "r"(b[1]));
}
__device__ __forceinline__ uint32_t pack_h2(float x, float y) {
    __half2 h = __floats2half2_rn(x, y);
    return *reinterpret_cast<uint32_t*>(&h);
}
// raw ex2.approx: one MUFU op, ex2(-inf) = 0
__device__ __forceinline__ float ex2(float x) {
    float y;
    asm("ex2.approx.f32 %0, %1;" : "=f"(y) : "f"(x));
    return y;
}
// PDL: allow dependents to launch; wait for upstream grid's memory
__device__ __forceinline__ void gd_launch() {
    asm volatile("griddepcontrol.launch_dependents;");
}
__device__ __forceinline__ void gd_wait() {
    asm volatile("griddepcontrol.wait;" ::: "memory");
}

// ---------------------------------------------------------------------------
// Fused fp32 -> fp16 convert; 4 independent float4 units per thread (MLP=4).
// ---------------------------------------------------------------------------
__global__ __launch_bounds__(256) void conv_all(
    const float* __restrict__ X,
    const float* __restrict__ Wq, const float* __restrict__ Wk,
    const float* __restrict__ Wv, const float* __restrict__ Wo,
    __half* __restrict__ xf, __half* __restrict__ wf)
{
    gd_launch();
    const int base = blockIdx.x * 1024 + threadIdx.x;
#pragma unroll
    for (int u = 0; u < 4; u++) {
        int i = base + u * 256;               // 0 .. 2^21-1
        const float* src;
        __half* dst;
        if (i < (1 << 20)) {
            src = X + (size_t)i * 4;
            dst = xf + (size_t)i * 4;
        } else {
            int j = i - (1 << 20);
            int sel = j >> 18;
            int jj = j & ((1 << 18) - 1);
            const float* w4[4] = {Wq, Wk, Wv, Wo};
            src = w4[sel] + (size_t)jj * 4;
            dst = wf + (size_t)sel * DMODEL * DMODEL + (size_t)jj * 4;
        }
        float4 v = *(const float4*)src;
        uint2 o;
        o.x = pack_h2(v.x, v.y);
        o.y = pack_h2(v.z, v.w);
        *(uint2*)dst = o;
    }
}

// ---------------------------------------------------------------------------
// Core A (qkv): 128x128 CTA tile, BK=32, 8 warps 2x4, warp 64x32.
// 3-stage ring; kk-level fragment double-buffering. (R12-R15 verified.)
// ---------------------------------------------------------------------------
#define STG128 20480
struct Gemm128 {
    uint32_t sbase;
    int tid, lane, wm, wn;
    uint32_t arow, ahalf, brow, bhalf;
    float c[4][4][4];

    __device__ __forceinline__ void init(uint32_t sb, int t) {
        sbase = sb; tid = t; lane = t & 31;
        int wid = t >> 5; wm = wid >> 2; wn = wid & 3;
        arow = lane & 15; ahalf = (uint32_t)(lane >> 4);
        brow = (lane & 7) | (((uint32_t)lane >> 4) << 3);
        bhalf = ((uint32_t)lane >> 3) & 1;
#pragma unroll
        for (int i = 0; i < 4; i++)
#pragma unroll
            for (int j = 0; j < 4; j++)
#pragma unroll
                for (int q = 0; q < 4; q++) c[i][j][q] = 0.f;
    }
    __device__ __forceinline__ void load_stage(const __half* A, const __half* B,
                                               int m0, int n0, int kt, int st) {
        const uint32_t dstb = sbase + st * STG128;
#pragma unroll
        for (int i = 0; i < 4; i++) {
            int cid = i * 256 + tid;            // 0..1023
            int t   = cid >> 9;                 // 0:A 1:B
            int row = (cid >> 2) & 127;
            int kc  = cid & 3;
            const __half* src = t ? B : A;
            const int gbase = t ? n0 : m0;
            cp16(dstb + t * 10240 + row * 80 + kc * 16,
                 src + (size_t)(gbase + row) * DMODEL + kt + kc * 8);
        }
    }
    __device__ __forceinline__ void run(const __half* A, const __half* B, int m0, int n0) {
        const int NK = DMODEL / 32;
        load_stage(A, B, m0, n0, 0, 0); cp_commit();
        load_stage(A, B, m0, n0, 32, 1); cp_commit();
        for (int ch = 0; ch < NK; ch++) {
            if (ch + 1 < NK) cp_wait<1>(); else cp_wait<0>();
            __syncthreads();
            const uint32_t tb = sbase + (ch % 3) * STG128;
            const uint32_t abase = tb + (wm * 64 + arow) * 80 + ahalf * 16;
            const uint32_t bbase = tb + 10240 + (wn * 32 + brow) * 80 + bhalf * 16;
            uint32_t ah[2][4][4], bb[2][2][4];
#pragma unroll
            for (int i = 0; i < 4; i++) ldsm4(ah[0][i], abase + i * (16 * 80));
#pragma unroll
            for (int j = 0; j < 2; j++) ldsm4(bb[0][j], bbase + j * (16 * 80));
            if (ch + 2 < NK) {
                load_stage(A, B, m0, n0, (ch + 2) * 32, (ch + 2) % 3);
                cp_commit();
            }
#pragma unroll
            for (int kk = 0; kk < 2; kk++) {
                const int cur = kk & 1, nxt = cur ^ 1;
                if (kk < 1) {
#pragma unroll
                    for (int i = 0; i < 4; i++) ldsm4(ah[nxt][i], abase + i * (16 * 80) + 32);
#pragma unroll
                    for (int j = 0; j < 2; j++) ldsm4(bb[nxt][j], bbase + j * (16 * 80) + 32);
                }
#pragma unroll
                for (int i = 0; i < 4; i++)
#pragma unroll
                    for (int j = 0; j < 4; j++)
                        mma16816(c[i][j], ah[cur][i], &bb[cur][j >> 1][(j & 1) * 2]);
            }
        }
    }
};

// Fused QKV projection: grid.x = 24 (seg = bx>>3, n0 = (bx&7)*128), grid.y = 32.
__global__ __launch_bounds__(256) void gemm_qkv(
    const __half* __restrict__ Xf, const __half* __restrict__ Wf,
    const float* __restrict__ bq, const float* __restrict__ bk,
    const float* __restrict__ bv,
    __half* __restrict__ Qf, __half* __restrict__ Kf, __half* __restrict__ Vf)
{
    extern __shared__ __align__(128) char smem[];
    gd_launch();
    const int seg = blockIdx.x >> 3;
    const int n0  = (blockIdx.x & 7) * 128;
    const int m0  = blockIdx.y * 128;
    const __half* B = Wf + (size_t)seg * DMODEL * DMODEL;
    const float* bias = (seg == 0) ? bq : (seg == 1) ? bk : bv;
    __half* Ch = (seg == 0) ? Qf : (seg == 1) ? Kf : Vf;
    // Q scale folds HD^-0.5 AND log2(e) so attention can use raw ex2.
    const float alpha = (seg == 0) ? 0.18033688f : 1.f;   // 0.125 * log2(e)

    Gemm128 g;
    g.init(smem_to_u32(smem), threadIdx.x);
    gd_wait();   // xf/wf produced by conv_all
    g.run(Xf, B, m0, n0);

    const int lane = g.lane;
#pragma unroll
    for (int i = 0; i < 4; i++) {
        const int r = m0 + g.wm * 64 + i * 16 + (lane >> 2);
#pragma unroll
        for (int j = 0; j < 4; j++) {
            const int col = n0 + g.wn * 32 + j * 8 + (lane & 3) * 2;
            const float b0 = bias[col], b1 = bias[col + 1];
            *(uint32_t*)(Ch + (size_t)r * DMODEL + col) =
                pack_h2(alpha * (g.c[i][j][0] + b0), alpha * (g.c[i][j][1] + b1));
            *(uint32_t*)(Ch + (size_t)(r + 8) * DMODEL + col) =
                pack_h2(alpha * (g.c[i][j][2] + b0), alpha * (g.c[i][j][3] + b1));
        }
    }
}

// ---------------------------------------------------------------------------
// Core B (out, R9-R15 verified): 128x256 CTA tile, warp 64x64,
// batch-fragment scheduling. Stage 30720 B, 3-stage ring.
// ---------------------------------------------------------------------------
#define STG256 30720
struct Gemm256 {
    uint32_t sbase;
    int tid, lane, wm, wn;
    uint32_t arow, ahalf, brow, bhalf;
    float c[4][8][4];

    __device__ __forceinline__ void init(uint32_t sb, int t) {
        sbase = sb; tid = t; lane = t & 31;
        int wid = t >> 5; wm = wid >> 2; wn = wid & 3;
        arow = lane & 15; ahalf = (uint32_t)(lane >> 4);
        brow = (lane & 7) | (((uint32_t)lane >> 4) << 3);
        bhalf = ((uint32_t)lane >> 3) & 1;
#pragma unroll
        for (int i = 0; i < 4; i++)
#pragma unroll
            for (int j = 0; j < 8; j++)
#pragma unroll
                for (int q = 0; q < 4; q++) c[i][j][q] = 0.f;
    }
    __device__ __forceinline__ void load_stage(const __half* A, const __half* B,
                                               int m0, int n0, int kt, int st) {
        const uint32_t dstb = sbase + st * STG256;
#pragma unroll
        for (int i = 0; i < 2; i++) {
            int cid = i * 256 + tid;
            int row = (cid & 7) | ((cid >> 5) << 3);
            int kc  = (cid >> 3) & 3;
            cp16(dstb + row * 80 + kc * 16,
                 A + (size_t)(m0 + row) * DMODEL + kt + kc * 8);
        }
#pragma unroll
        for (int i = 0; i < 4; i++) {
            int cid = i * 256 + tid;
            int row = (cid & 7) | ((cid >> 5) << 3);
            int kc  = (cid >> 3) & 3;
            cp16(dstb + 10240 + row * 80 + kc * 16,
                 B + (size_t)(n0 + row) * DMODEL + kt + kc * 8);
        }
    }
    __device__ __forceinline__ void run(const __half* A, const __half* B, int m0, int n0) {
        const int NK = DMODEL / 32;
        load_stage(A, B, m0, n0, 0, 0); cp_commit();
        load_stage(A, B, m0, n0, 32, 1); cp_commit();
        for (int ch = 0; ch < NK; ch++) {
            if (ch + 1 < NK) cp_wait<1>(); else cp_wait<0>();
            __syncthreads();
            const uint32_t tb = sbase + (ch % 3) * STG256;
            uint32_t ah[2][4][4], bb[2][4][4];
#pragma unroll
            for (int kk = 0; kk < 2; kk++) {
                const uint32_t koff = kk * 32;
#pragma unroll
                for (int i = 0; i < 4; i++)
                    ldsm4(ah[kk][i], tb + (wm * 64 + i * 16 + arow) * 80 + koff + ahalf * 16);
#pragma unroll
                for (int j = 0; j < 4; j++)
                    ldsm4(bb[kk][j], tb + 10240 + (wn * 64 + j * 16 + brow) * 80 + koff + bhalf * 16);
            }
            if (ch + 2 < NK) {
                load_stage(A, B, m0, n0, (ch + 2) * 32, (ch + 2) % 3);
                cp_commit();
            }
#pragma unroll
            for (int kk = 0; kk < 2; kk++)
#pragma unroll
                for (int i = 0; i < 4; i++)
#pragma unroll
                    for (int j = 0; j < 8; j++)
                        mma16816(c[i][j], ah[kk][i], &bb[kk][j >> 1][(j & 1) * 2]);
        }
    }
};

// Output projection: fp32 output. grid (4, 32) = 128 CTAs (one wave).
__global__ __launch_bounds__(256) void gemm_out(
    const __half* __restrict__ A, const __half* __restrict__ B,
    const float* __restrict__ bias, float* __restrict__ Cf)
{
    extern __shared__ __align__(128) char smem[];
    gd_launch();
    const int n0 = blockIdx.x * 256;
    const int m0 = blockIdx.y * 128;

    Gemm256 g;
    g.init(smem_to_u32(smem), threadIdx.x);
    gd_wait();   // af produced by attn_tc
    g.run(A, B, m0, n0);

    const int lane = g.lane;
#pragma unroll
    for (int i = 0; i < 4; i++) {
        const int r = m0 + g.wm * 64 + i * 16 + (lane >> 2);
#pragma unroll
        for (int j = 0; j < 8; j++) {
            const int col = n0 + g.wn * 64 + j * 8 + (lane & 3) * 2;
            const float b0 = bias[col], b1 = bias[col + 1];
            float2 w0, w1;
            w0.x = g.c[i][j][0] + b0; w0.y = g.c[i][j][1] + b1;
            w1.x = g.c[i][j][2] + b0; w1.y = g.c[i][j][3] + b1;
            *(float2*)(Cf + (size_t)r * DMODEL + col)       = w0;
            *(float2*)(Cf + (size_t)(r + 8) * DMODEL + col) = w1;
        }
    }
}

// ---------------------------------------------------------------------------
// fp16 HMMA flash attention, causal, NO-MAX streaming softmax with raw ex2.
// Q fragments hoisted to registers once (kt==0). exp inside PV loop.
// CTA = (128-q tile, head, batch), 256 thr. K/V tiles 64 rows, 3-stage ring.
// smem (73728 B): Q@0 (128x144); stage s at 18432 + s*18432: K@+0, V@+9216.
// ---------------------------------------------------------------------------
__global__ __launch_bounds__(256) void attn_tc(
    const __half* __restrict__ Q, const __half* __restrict__ K,
    const __half* __restrict__ V, __half* __restrict__ O)
{
    extern __shared__ __align__(128) char smem[];
    gd_launch();
    const uint32_t sb = smem_to_u32(smem);
    const int tid = threadIdx.x, lane = tid & 31, w = tid >> 5;
    const int qt = 15 - blockIdx.x;      // heavy tiles first
    const int h  = blockIdx.y;
    const int b  = blockIdx.z;
    const size_t tokq = (size_t)b * 2048 + qt * 128;
    const size_t hoff = (size_t)h * HDIM;

    auto load_kv = [&](int kt, int s) {
        const size_t tokk = (size_t)b * 2048 + kt * 64;
        const uint32_t db = sb + 18432 + s * 18432;
#pragma unroll
        for (int i = 0; i < 4; i++) {
            int c = tid + i * 256;
            int t = c >> 9, r = (c >> 3) & 63, kc = c & 7;
            const __half* src = t ? V : K;
            cp16(db + t * 9216 + r * 144 + kc * 16, src + (tokk + r) * DMODEL + hoff + kc * 8);
        }
    };

    gd_wait();   // qf/kf/vf produced by gemm_qkv
#pragma unroll
    for (int i = 0; i < 4; i++) {
        int c = tid + i * 256;
        int r = c >> 3, kc = c & 7;
        cp16(sb + r * 144 + kc * 16, Q + (tokq + r) * DMODEL + hoff + kc * 8);
    }
    const int kmax = 2 * qt + 1;
    load_kv(0, 0); cp_commit();
    load_kv(1, 1); cp_commit();

    float o[8][4];
#pragma unroll
    for (int nb = 0; nb < 8; nb++)
#pragma unroll
        for (int q = 0; q < 4; q++) o[nb][q] = 0.f;
    float l0 = 0.f, l1 = 0.f;

    const uint32_t qa  = (uint32_t)((w * 16 + (lane & 15)) * 144 + (lane >> 4) * 16);
    const uint32_t kbr = (uint32_t)((lane & 7) | ((lane >> 4) << 3));
    const uint32_t kbh = (uint32_t)(((lane >> 3) & 1) * 16);
    const uint32_t vkr = (uint32_t)((lane & 7) + ((lane >> 3) & 1) * 8);
    const uint32_t vnc = (uint32_t)(((lane >> 4) & 1) * 8);

    const int gr0 = qt * 128 + w * 16 + (lane >> 2);
    const int gr1 = gr0 + 8;

    uint32_t aqall[4][4];   // Q fragments, loaded once at kt==0, live all loop

    for (int kt = 0; kt <= kmax; kt++) {
        if (kt + 1 <= kmax) cp_wait<1>(); else cp_wait<0>();
        __syncthreads();
        if (kt + 2 <= kmax) { load_kv(kt + 2, (kt + 2) % 3); cp_commit(); }

        const uint32_t KB = sb + 18432 + (kt % 3) * 18432;
        const uint32_t VB = KB + 9216;

        if (kt == 0) {   // hoist: Q is ready after the first group wait
#pragma unroll
            for (int kk = 0; kk < 4; kk++)
                ldsm4(aqall[kk], sb + qa + kk * 32);
        }

        // ---- S = Q K^T (K fragments double-buffered; Q in registers) ----
        float sfr[8][4];
#pragma unroll
        for (int nb = 0; nb < 8; nb++)
#pragma unroll
            for (int q = 0; q < 4; q++) sfr[nb][q] = 0.f;

        uint32_t bk4[2][4][4];
#pragma unroll
        for (int t = 0; t < 4; t++)
            ldsm4(bk4[0][t], KB + (t * 16 + kbr) * 144 + kbh);
#pragma unroll
        for (int kk = 0; kk < 4; kk++) {
            const int cur = kk & 1, nxt = cur ^ 1;
            if (kk < 3) {
#pragma unroll
                for (int t = 0; t < 4; t++)
                    ldsm4(bk4[nxt][t], KB + (t * 16 + kbr) * 144 + (kk + 1) * 32 + kbh);
            }
#pragma unroll
            for (int nb = 0; nb < 8; nb++)
                mma16816(sfr[nb], aqall[kk], &bk4[cur][nb >> 1][(nb & 1) * 2]);
        }

        // causal mask (only the last two K tiles can intersect the diagonal)
        if (kt >= kmax - 1) {
            const int cb = kt * 64;
#pragma unroll
            for (int nb = 0; nb < 8; nb++) {
                const int cc = cb + nb * 8 + (lane & 3) * 2;
                if (cc     > gr0) sfr[nb][0] = -INFINITY;
                if (cc + 1 > gr0) sfr[nb][1] = -INFINITY;
                if (cc     > gr1) sfr[nb][2] = -INFINITY;
                if (cc + 1 > gr1) sfr[nb][3] = -INFINITY;
            }
        }

        // ---- O += P V; exp (ex2) per-kk inside the loop (MUFU overlap) ----
        uint32_t vv[2][4][4];
#pragma unroll
        for (int t = 0; t < 4; t++)
            ldsm4t(vv[0][t], VB + vkr * 144 + (t * 16 + vnc) * 2);
#pragma unroll
        for (int kk = 0; kk < 4; kk++) {
            const int cur = kk & 1, nxt = cur ^ 1;
            if (kk < 3) {
#pragma unroll
                for (int t = 0; t < 4; t++)
                    ldsm4t(vv[nxt][t], VB + ((kk + 1) * 16 + vkr) * 144 + (t * 16 + vnc) * 2);
            }
            float* p0 = sfr[2 * kk];
            float* p1 = sfr[2 * kk + 1];
            p0[0] = ex2(p0[0]); p0[1] = ex2(p0[1]);
            p0[2] = ex2(p0[2]); p0[3] = ex2(p0[3]);
            p1[0] = ex2(p1[0]); p1[1] = ex2(p1[1]);
            p1[2] = ex2(p1[2]); p1[3] = ex2(p1[3]);
            l0 += p0[0] + p0[1] + p1[0] + p1[1];
            l1 += p0[2] + p0[3] + p1[2] + p1[3];
            uint32_t ap[4];
            ap[0] = pack_h2(p0[0], p0[1]);
            ap[1] = pack_h2(p0[2], p0[3]);
            ap[2] = pack_h2(p1[0], p1[1]);
            ap[3] = pack_h2(p1[2], p1[3]);
#pragma unroll
            for (int nb = 0; nb < 8; nb++)
                mma16816(o[nb], ap, &vv[cur][nb >> 1][(nb & 1) * 2]);
        }
    }

    // row-sum reduce across the 4-lane quad, then normalize + store
    l0 += __shfl_xor_sync(0xffffffffu, l0, 1);
    l0 += __shfl_xor_sync(0xffffffffu, l0, 2);
    l1 += __shfl_xor_sync(0xffffffffu, l1, 1);
    l1 += __shfl_xor_sync(0xffffffffu, l1, 2);
    const float i0 = 1.f / l0, i1 = 1.f / l1;
    const size_t r0 = tokq + w * 16 + (lane >> 2);
    const size_t r1 = r0 + 8;
#pragma unroll
    for (int nb = 0; nb < 8; nb++) {
        const size_t col = hoff + nb * 8 + (lane & 3) * 2;
        *(uint32_t*)(O + r0 * DMODEL + col) = pack_h2(o[nb][0] * i0, o[nb][1] * i0);
        *(uint32_t*)(O + r1 * DMODEL + col) = pack_h2(o[nb][2] * i1, o[nb][3] * i1);
    }
}

// ---------------------------------------------------------------------------
// Residual add + LayerNorm
// ---------------------------------------------------------------------------
__global__ __launch_bounds__(256) void ln_kernel(
    const float* __restrict__ Osrc, const float* __restrict__ X,
    const float* __restrict__ g, const float* __restrict__ beta,
    float* __restrict__ out)
{
    gd_wait();   // Ob produced by gemm_out
    const int row = blockIdx.x;
    const int tid = threadIdx.x;
    const float* o = Osrc + (size_t)row * DMODEL;
    const float* x = X + (size_t)row * DMODEL;

    float v[4];
    float s = 0.f, s2 = 0.f;
#pragma unroll
    for (int i = 0; i < 4; i++) {
        int c = tid + i * 256;
        float t = o[c] + x[c];
        v[i] = t; s += t; s2 += t * t;
    }
#pragma unroll
    for (int off = 16; off; off >>= 1) {
        s  += __shfl_xor_sync(0xffffffffu, s, off);
        s2 += __shfl_xor_sync(0xffffffffu, s2, off);
    }
    __shared__ float red[18];
    int w = tid >> 5;
    if ((tid & 31) == 0) { red[w] = s; red[8 + w] = s2; }
    __syncthreads();
    if (tid == 0) {
        float S = 0.f, S2 = 0.f;
        for (int k = 0; k < 8; k++) { S += red[k]; S2 += red[8 + k]; }
        red[16] = S; red[17] = S2;
    }
    __syncthreads();
    float mu   = red[16] * (1.f / 1024.f);
    float var  = red[17] * (1.f / 1024.f) - mu * mu;
    float rstd = rsqrtf(var + 1e-5f);
#pragma unroll
    for (int i = 0; i < 4; i++) {
        int c = tid + i * 256;
        out[(size_t)row * DMODEL + c] = (v[i] - mu) * rstd * g[c] + beta[c];
    }
}

// ---------------------------------------------------------------------------
extern "C" void kernel_launch(void* const* d_in, const int* in_sizes, int n_in,
                              void* d_out, int out_size)
{
    const float* X  = (const float*)d_in[0];
    const float* Wq = (const float*)d_in[1];
    const float* bq = (const float*)d_in[2];
    const float* Wk = (const float*)d_in[3];
    const float* bk = (const float*)d_in[4];
    const float* Wv = (const float*)d_in[5];
    const float* bv = (const float*)d_in[6];
    const float* Wo = (const float*)d_in[7];
    const float* bo = (const float*)d_in[8];
    const float* lg = (const float*)d_in[9];
    const float* lb = (const float*)d_in[10];
    float* out = (float*)d_out;

    float* Ob = nullptr;
    cudaGetSymbolAddress((void**)&Ob, g_ob);
    __half *xf, *qf, *kf, *vf, *af, *wf;
    cudaGetSymbolAddress((void**)&xf, g_xf);
    cudaGetSymbolAddress((void**)&qf, g_qf);
    cudaGetSymbolAddress((void**)&kf, g_kf);
    cudaGetSymbolAddress((void**)&vf, g_vf);
    cudaGetSymbolAddress((void**)&af, g_af);
    cudaGetSymbolAddress((void**)&wf, g_wf);

    const size_t WS = (size_t)DMODEL * DMODEL;

    cudaFuncSetAttribute(gemm_qkv, cudaFuncAttributeMaxDynamicSharedMemorySize, 3 * STG128);
    cudaFuncSetAttribute(gemm_out, cudaFuncAttributeMaxDynamicSharedMemorySize, 3 * STG256);
    const int attn_smem = 18432 + 3 * 18432;    // 73,728 B
    cudaFuncSetAttribute(attn_tc, cudaFuncAttributeMaxDynamicSharedMemorySize, attn_smem);

    // PDL attribute: dependent kernels may launch while predecessor drains.
    cudaLaunchAttribute pdl[1];
    pdl[0].id = cudaLaunchAttributeProgrammaticStreamSerialization;
    pdl[0].val.programmaticStreamSerializationAllowed = 1;

    conv_all<<<(1 << 21) / 1024, 256>>>(X, Wq, Wk, Wv, Wo, xf, wf);

    {
        cudaLaunchConfig_t cfg{};
        cfg.gridDim = dim3(24, 32); cfg.blockDim = dim3(256);
        cfg.dynamicSmemBytes = 3 * STG128; cfg.stream = 0;
        cfg.attrs = pdl; cfg.numAttrs = 1;
        cudaLaunchKernelEx(&cfg, gemm_qkv, (const __half*)xf, (const __half*)wf,
                           bq, bk, bv, qf, kf, vf);
    }
    {
        cudaLaunchConfig_t cfg{};
        cfg.gridDim = dim3(16, NHEAD, 2); cfg.blockDim = dim3(256);
        cfg.dynamicSmemBytes = attn_smem; cfg.stream = 0;
        cfg.attrs = pdl; cfg.numAttrs = 1;
        cudaLaunchKernelEx(&cfg, attn_tc, (const __half*)qf, (const __half*)kf,
                           (const __half*)vf, af);
    }
    {
        cudaLaunchConfig_t cfg{};
        cfg.gridDim = dim3(4, 32); cfg.blockDim = dim3(256);
        cfg.dynamicSmemBytes = 3 * STG256; cfg.stream = 0;
        cfg.attrs = pdl; cfg.numAttrs = 1;
        cudaLaunchKernelEx(&cfg, gemm_out, (const __half*)af,
                           (const __half*)(wf + 3 * WS), bo, Ob);
    }
    {
        cudaLaunchConfig_t cfg{};
        cfg.gridDim = dim3(M_TOK); cfg.blockDim = dim3(256);
        cfg.dynamicSmemBytes = 0; cfg.stream = 0;
        cfg.attrs = pdl; cfg.numAttrs = 1;
        cudaLaunchKernelEx(&cfg, ln_kernel, (const float*)Ob, X, lg, lb, out);
    }
}